// round 4
// baseline (speedup 1.0000x reference)
#include <cuda_runtime.h>
#include <cuda_bf16.h>
#include <cstdint>
#include <cstddef>

#define BATCH    8
#define NPTS     8192
#define NPOINT_  1024
#define NSAMPLE_ 32
#define CFEAT    64
#define CSZ      4
#define PPC      (NPTS / CSZ)   // 2048 points per CTA

// scratch (device globals; no allocation allowed)
__device__ int   g_gidx[BATCH * NPOINT_ * NSAMPLE_];   // ball-query neighbor indices
__device__ float g_featproj[BATCH * NPTS * CFEAT];     // W1[:,3:] @ features per unique point

// ---------------- f32x2 helpers (Blackwell packed fp32; IEEE per lane) ------
__device__ __forceinline__ unsigned long long f2_pack(float a, float b) {
    unsigned long long r;
    asm("mov.b64 %0, {%1, %2};" : "=l"(r) : "r"(__float_as_uint(a)), "r"(__float_as_uint(b)));
    return r;
}
__device__ __forceinline__ unsigned long long f2_bcast(float a) {
    unsigned long long r;
    unsigned x = __float_as_uint(a);
    asm("mov.b64 %0, {%1, %1};" : "=l"(r) : "r"(x));
    return r;
}
__device__ __forceinline__ void f2_unpack(unsigned long long v, float& lo, float& hi) {
    unsigned a, b;
    asm("mov.b64 {%0, %1}, %2;" : "=r"(a), "=r"(b) : "l"(v));
    lo = __uint_as_float(a); hi = __uint_as_float(b);
}
__device__ __forceinline__ unsigned long long f2_add(unsigned long long a, unsigned long long b) {
    unsigned long long d;
    asm("add.rn.f32x2 %0, %1, %2;" : "=l"(d) : "l"(a), "l"(b));
    return d;
}
__device__ __forceinline__ unsigned long long f2_mul(unsigned long long a, unsigned long long b) {
    unsigned long long d;
    asm("mul.rn.f32x2 %0, %1, %2;" : "=l"(d) : "l"(a), "l"(b));
    return d;
}
__device__ __forceinline__ unsigned long long f2_fma(unsigned long long a, unsigned long long b,
                                                     unsigned long long c) {
    unsigned long long d;
    asm("fma.rn.f32x2 %0, %1, %2, %3;" : "=l"(d) : "l"(a), "l"(b), "l"(c));
    return d;
}
__device__ __forceinline__ unsigned smem_u32(const void* p) {
    return (unsigned)__cvta_generic_to_shared(p);
}

// ---------------------------------------------------------------------------
// Kernel 1: farthest point sampling. Cluster of 4 CTAs per batch (32 CTAs).
// Each CTA: 2048 pts in regs (f32x2 pairs), full 8192-pt cloud in 96KB smem
// for winner lookup. Per-iteration cross-CTA exchange of the u64 winner key
// (distbits<<32 | 8191-idx) via DSMEM stores + mbarrier (double-buffered).
// Per-point arithmetic is bitwise identical to the passing scalar version.
// ---------------------------------------------------------------------------
__global__ void __cluster_dims__(CSZ, 1, 1) __launch_bounds__(512, 1)
fps_kernel(const float* __restrict__ xyz, float* __restrict__ newxyz)
{
    extern __shared__ float fsm[];
    float* sx = fsm;
    float* sy = fsm + NPTS;
    float* sz = fsm + 2 * NPTS;
    __shared__ unsigned long long mbox[2][CSZ];
    __shared__ unsigned long long mbar[2];
    __shared__ unsigned long long wkey[16];

    const int t = threadIdx.x;
    unsigned rank;
    asm("mov.u32 %0, %%cluster_ctarank;" : "=r"(rank));
    const int b = blockIdx.x / CSZ;
    const float* xb = xyz + (size_t)b * NPTS * 3;

    for (int i = t; i < NPTS; i += 512) {
        sx[i] = xb[3 * i + 0];
        sy[i] = xb[3 * i + 1];
        sz[i] = xb[3 * i + 2];
    }
    if (t == 0) {
        asm volatile("mbarrier.init.shared.b64 [%0], %1;" :: "r"(smem_u32(&mbar[0])), "r"((unsigned)CSZ) : "memory");
        asm volatile("mbarrier.init.shared.b64 [%0], %1;" :: "r"(smem_u32(&mbar[1])), "r"((unsigned)CSZ) : "memory");
    }
    __syncthreads();
    asm volatile("barrier.cluster.arrive.aligned;" ::: "memory");
    asm volatile("barrier.cluster.wait.aligned;" ::: "memory");

    const int base = (int)rank * PPC;
    unsigned long long px2[2], py2[2], pz2[2];
    float pd[4];
#pragma unroll
    for (int q = 0; q < 2; ++q) {
        int i0 = base + t + (2 * q) * 512;
        int i1 = i0 + 512;
        px2[q] = f2_pack(sx[i0], sx[i1]);
        py2[q] = f2_pack(sy[i0], sy[i1]);
        pz2[q] = f2_pack(sz[i0], sz[i1]);
        pd[2 * q] = 1e10f; pd[2 * q + 1] = 1e10f;
    }

    float lx = sx[0], ly = sy[0], lz = sz[0];
    if (rank == 0 && t == 0) {
        newxyz[b * NPOINT_ * 3 + 0] = lx;
        newxyz[b * NPOINT_ * 3 + 1] = ly;
        newxyz[b * NPOINT_ * 3 + 2] = lz;
    }
    const int lane = t & 31, wid = t >> 5;
    int ph0 = 0, ph1 = 0;

    for (int it = 1; it < NPOINT_; ++it) {
        const unsigned long long nlx = f2_bcast(-lx);
        const unsigned long long nly = f2_bcast(-ly);
        const unsigned long long nlz = f2_bcast(-lz);
#pragma unroll
        for (int q = 0; q < 2; ++q) {
            unsigned long long dx = f2_add(px2[q], nlx);
            unsigned long long dy = f2_add(py2[q], nly);
            unsigned long long dz = f2_add(pz2[q], nlz);
            unsigned long long d2 = f2_fma(dx, dx, f2_fma(dy, dy, f2_mul(dz, dz)));
            float d0, d1;
            f2_unpack(d2, d0, d1);
            pd[2 * q]     = fminf(pd[2 * q],     d0);
            pd[2 * q + 1] = fminf(pd[2 * q + 1], d1);
        }
        const float vmax = fmaxf(fmaxf(pd[0], pd[1]), fmaxf(pd[2], pd[3]));
        unsigned msk = 0;
#pragma unroll
        for (int j = 0; j < 4; ++j) msk |= (pd[j] == vmax) ? (1u << j) : 0u;
        const int bj = __ffs(msk) - 1;
        const unsigned gi = (unsigned)(base + t + bj * 512);

        const unsigned vb = __float_as_uint(vmax);
        const unsigned wm = __reduce_max_sync(0xffffffffu, vb);
        const unsigned cand = (vb == wm) ? gi : 0xffffffffu;
        const unsigned wi = __reduce_min_sync(0xffffffffu, cand);
        const unsigned long long key =
            ((unsigned long long)wm << 32) | (unsigned)(8191 - wi);

        if (lane == 0) wkey[wid] = key;
        __syncthreads();

        const int buf = it & 1;
        const unsigned lbar = smem_u32(&mbar[buf]);
        if (wid == 0) {
            const unsigned long long k = wkey[lane & 15];
            const unsigned hi = (unsigned)(k >> 32);
            const unsigned lo = (unsigned)k;
            const unsigned hm = __reduce_max_sync(0xffffffffu, hi);
            const unsigned cl = (hi == hm) ? lo : 0u;
            const unsigned lm = __reduce_max_sync(0xffffffffu, cl);
            const unsigned long long ck = ((unsigned long long)hm << 32) | lm;
            if (lane < CSZ) {
                const unsigned lmb = smem_u32(&mbox[buf][rank]);
                unsigned rmb, rbr;
                asm("mapa.shared::cluster.u32 %0, %1, %2;" : "=r"(rmb) : "r"(lmb), "r"(lane));
                asm("mapa.shared::cluster.u32 %0, %1, %2;" : "=r"(rbr) : "r"(lbar), "r"(lane));
                asm volatile("st.shared::cluster.b64 [%0], %1;" :: "r"(rmb), "l"(ck) : "memory");
                asm volatile("mbarrier.arrive.release.cluster.shared::cluster.b64 _, [%0];"
                             :: "r"(rbr) : "memory");
            }
        }
        const unsigned p = (unsigned)(buf ? ph1 : ph0);
        unsigned ok;
        do {
            asm volatile(
                "{ .reg .pred P;\n\t"
                "mbarrier.try_wait.parity.acquire.cluster.shared::cta.b64 P, [%1], %2, 0x989680;\n\t"
                "selp.b32 %0, 1, 0, P; }"
                : "=r"(ok) : "r"(lbar), "r"(p) : "memory");
        } while (!ok);
        if (buf) ph1 ^= 1; else ph0 ^= 1;

        const unsigned long long k0 = mbox[buf][0];
        const unsigned long long k1 = mbox[buf][1];
        const unsigned long long k2 = mbox[buf][2];
        const unsigned long long k3 = mbox[buf][3];
        unsigned long long m01 = (k0 > k1) ? k0 : k1;
        unsigned long long m23 = (k2 > k3) ? k2 : k3;
        unsigned long long km  = (m01 > m23) ? m01 : m23;
        const int win = 8191 - (int)(unsigned)(km & 0xffffffffull);
        lx = sx[win]; ly = sy[win]; lz = sz[win];
        if (rank == 0 && t == 0) {
            newxyz[(b * NPOINT_ + it) * 3 + 0] = lx;
            newxyz[(b * NPOINT_ + it) * 3 + 1] = ly;
            newxyz[(b * NPOINT_ + it) * 3 + 2] = lz;
        }
    }
    asm volatile("barrier.cluster.arrive.aligned;" ::: "memory");
    asm volatile("barrier.cluster.wait.aligned;" ::: "memory");
}

// ---------------------------------------------------------------------------
// Kernel 2: layer-1 feature projection for all unique points.
// ---------------------------------------------------------------------------
__global__ void __launch_bounds__(256) featproj_kernel(const float* __restrict__ feat,
                                                       const float* __restrict__ w1)
{
    __shared__ float ws[64 * 65];
    __shared__ float sf[8][64];

    const int tid = threadIdx.x;
    for (int i = tid; i < 64 * 64; i += 256) {
        int o = i >> 6, c = i & 63;
        ws[o * 65 + c] = w1[o * 67 + 3 + c];
    }
    __syncthreads();

    const int wid = tid >> 5, lane = tid & 31;
    const int row = blockIdx.x * 8 + wid;
    const float* fr = feat + (size_t)row * 64;
    sf[wid][lane]      = fr[lane];
    sf[wid][lane + 32] = fr[lane + 32];
    __syncwarp();

    float a0 = 0.f, a1 = 0.f;
#pragma unroll
    for (int c = 0; c < 64; ++c) {
        float f = sf[wid][c];
        a0 = fmaf(ws[lane * 65 + c],        f, a0);
        a1 = fmaf(ws[(lane + 32) * 65 + c], f, a1);
    }
    float* outr = g_featproj + (size_t)row * 64;
    outr[lane]      = a0;
    outr[lane + 32] = a1;
}

// ---------------------------------------------------------------------------
// Kernel 3: ball query. One warp per center; first-32-by-index, pad with first.
// ---------------------------------------------------------------------------
__global__ void __launch_bounds__(256) ballquery_kernel(const float* __restrict__ xyz,
                                                        const float* __restrict__ newxyz)
{
    const int gw = (blockIdx.x * blockDim.x + threadIdx.x) >> 5;
    const int lane = threadIdx.x & 31;
    const int b = gw >> 10;
    const float* xb = xyz + (size_t)b * NPTS * 3;
    const float cx = newxyz[gw * 3 + 0];
    const float cy = newxyz[gw * 3 + 1];
    const float cz = newxyz[gw * 3 + 2];
    int* out = g_gidx + gw * 32;

    const float R2 = (float)(0.4 * 0.4);
    int cnt = 0, first = 0;
    bool hasfirst = false;
    for (int p0 = 0; p0 < NPTS && cnt < 32; p0 += 32) {
        int p = p0 + lane;
        float dx = xb[p * 3 + 0] - cx;
        float dy = xb[p * 3 + 1] - cy;
        float dz = xb[p * 3 + 2] - cz;
        float d2 = fmaf(dx, dx, fmaf(dy, dy, dz * dz));
        bool in = d2 < R2;
        unsigned mask = __ballot_sync(0xffffffffu, in);
        if (mask) {
            if (!hasfirst) { first = p0 + __ffs(mask) - 1; hasfirst = true; }
            int ofs = cnt + __popc(mask & ((1u << lane) - 1u));
            if (in && ofs < 32) out[ofs] = p;
            cnt += __popc(mask);
        }
    }
    for (int s = cnt + lane; s < 32; s += 32) out[s] = first;
}

// ---------------------------------------------------------------------------
// Kernel 4: fused gather + 3-layer MLP + max-pool. Warp per center, lane = sample.
// Layers 2/3 in packed f32x2; maxpool via REDUX on nonneg float bits.
// smem (floats):
//   [0,256)       w1p float4(w1x,w1y,w1z,b1) per out-channel
//   [256,320)     b2 (pairs read as u64)
//   [320,448)     b3
//   [448,4544)    w2t  [c 64][o 64]
//   [4544,12736)  w3p  [c2 32][o 128] float2 = (w3[o][2c2], w3[o][2c2+1])
//   [12736,13248) sout [o 128][warp 4]
// ---------------------------------------------------------------------------
__global__ void __launch_bounds__(128) mlp_kernel(
    const float* __restrict__ xyz,
    const float* __restrict__ w1, const float* __restrict__ b1,
    const float* __restrict__ w2, const float* __restrict__ b2,
    const float* __restrict__ w3, const float* __restrict__ b3,
    float* __restrict__ d_out)
{
    extern __shared__ float sm[];
    float4* sw1p = (float4*)sm;
    float*  sb2  = sm + 256;
    float*  sb3  = sm + 320;
    float*  sw2t = sm + 448;
    unsigned long long* sw3p = (unsigned long long*)(sm + 4544);
    float*  sout = sm + 12736;

    const int tid = threadIdx.x;
    const int wid = tid >> 5, lane = tid & 31;
    const int center0 = blockIdx.x * 4;
    const int center = center0 + wid;
    const int b = center >> 10;
    const int m0 = center0 & 1023;

    if (tid < 64) {
        sw1p[tid] = make_float4(w1[tid * 67 + 0], w1[tid * 67 + 1], w1[tid * 67 + 2], b1[tid]);
        sb2[tid] = b2[tid];
    }
    if (tid < 128) sb3[tid] = b3[tid];
    for (int i = tid; i < 4096; i += 128) sw2t[i] = w2[(i & 63) * 64 + (i >> 6)];
    for (int i = tid; i < 4096; i += 128) {
        int c2 = i >> 7, o = i & 127;
        ((float2*)sw3p)[i] = make_float2(w3[o * 64 + 2 * c2], w3[o * 64 + 2 * c2 + 1]);
    }
    __syncthreads();

    const float* newxyz = d_out;              // written by fps_kernel
    const float cx = newxyz[center * 3 + 0];
    const float cy = newxyz[center * 3 + 1];
    const float cz = newxyz[center * 3 + 2];

    const int ni = g_gidx[center * 32 + lane];
    const float* p = xyz + ((size_t)b * NPTS + ni) * 3;
    const float dx = p[0] - cx, dy = p[1] - cy, dz = p[2] - cz;

    // ---- layers 1+2 fused; h2 accumulated as output-pairs in f32x2 ----
    unsigned long long h2p[32];
#pragma unroll
    for (int k = 0; k < 32; ++k) h2p[k] = ((const unsigned long long*)sb2)[k];

    const float4* fp4 = (const float4*)(g_featproj + ((size_t)b * NPTS + ni) * 64);
#pragma unroll 1
    for (int cc = 0; cc < 16; ++cc) {
        float4 f = fp4[cc];
        float fv[4] = {f.x, f.y, f.z, f.w};
#pragma unroll
        for (int j = 0; j < 4; ++j) {
            int c = cc * 4 + j;
            float4 wp = sw1p[c];
            float a = fmaf(wp.x, dx, fv[j]);
            a = fmaf(wp.y, dy, a);
            a = fmaf(wp.z, dz, a);
            a = fmaxf(a + wp.w, 0.0f);
            const unsigned long long a2 = f2_bcast(a);
            const ulonglong2* wrow = (const ulonglong2*)(sw2t + c * 64);
#pragma unroll
            for (int k2 = 0; k2 < 16; ++k2) {
                ulonglong2 w = wrow[k2];
                h2p[2 * k2 + 0] = f2_fma(w.x, a2, h2p[2 * k2 + 0]);
                h2p[2 * k2 + 1] = f2_fma(w.y, a2, h2p[2 * k2 + 1]);
            }
        }
    }
#pragma unroll
    for (int k = 0; k < 32; ++k) {
        float lo, hi;
        f2_unpack(h2p[k], lo, hi);
        h2p[k] = f2_pack(fmaxf(lo, 0.0f), fmaxf(hi, 0.0f));
    }

    // ---- layer 3 (c-paired f32x2, even/odd partial sums) + REDUX max-pool ----
#pragma unroll 1
    for (int o8 = 0; o8 < 16; ++o8) {
        unsigned long long acc[8];
#pragma unroll
        for (int j = 0; j < 8; ++j) acc[j] = f2_pack(sb3[o8 * 8 + j], 0.0f);
#pragma unroll
        for (int c2 = 0; c2 < 32; ++c2) {
            const unsigned long long a = h2p[c2];
            const ulonglong2* wr = (const ulonglong2*)(sw3p + c2 * 128 + o8 * 8);
            ulonglong2 wa = wr[0], wb = wr[1], wc = wr[2], wd = wr[3];
            acc[0] = f2_fma(wa.x, a, acc[0]);
            acc[1] = f2_fma(wa.y, a, acc[1]);
            acc[2] = f2_fma(wb.x, a, acc[2]);
            acc[3] = f2_fma(wb.y, a, acc[3]);
            acc[4] = f2_fma(wc.x, a, acc[4]);
            acc[5] = f2_fma(wc.y, a, acc[5]);
            acc[6] = f2_fma(wd.x, a, acc[6]);
            acc[7] = f2_fma(wd.y, a, acc[7]);
        }
#pragma unroll
        for (int j = 0; j < 8; ++j) {
            float e, od;
            f2_unpack(acc[j], e, od);
            float v = fmaxf(e + od, 0.0f);
            unsigned r = __reduce_max_sync(0xffffffffu, __float_as_uint(v));
            if (lane == 0) sout[(o8 * 8 + j) * 4 + wid] = __uint_as_float(r);
        }
    }
    __syncthreads();

    float* nf = d_out + BATCH * NPOINT_ * 3;
    const int o = tid;
    float4 v = *(float4*)&sout[o * 4];
    *(float4*)&nf[((size_t)b * 128 + o) * (size_t)NPOINT_ + m0] = v;
}

// ---------------------------------------------------------------------------
extern "C" void kernel_launch(void* const* d_in, const int* in_sizes, int n_in,
                              void* d_out, int out_size)
{
    const float* xyz      = (const float*)d_in[0];
    const float* features = (const float*)d_in[1];
    const float* w1 = (const float*)d_in[2];
    const float* b1 = (const float*)d_in[3];
    const float* w2 = (const float*)d_in[4];
    const float* b2 = (const float*)d_in[5];
    const float* w3 = (const float*)d_in[6];
    const float* b3 = (const float*)d_in[7];
    float* out = (float*)d_out;

    cudaFuncSetAttribute(fps_kernel, cudaFuncAttributeMaxDynamicSharedMemorySize, NPTS * 3 * 4);
    cudaFuncSetAttribute(mlp_kernel, cudaFuncAttributeMaxDynamicSharedMemorySize, 13248 * 4);

    featproj_kernel<<<8192, 256>>>(features, w1);
    fps_kernel<<<BATCH * CSZ, 512, NPTS * 3 * 4>>>(xyz, out);
    ballquery_kernel<<<1024, 256>>>(xyz, out);
    mlp_kernel<<<2048, 128, 13248 * 4>>>(xyz, w1, b1, w2, b2, w3, b3, out);
}

// round 5
// speedup vs baseline: 1.3046x; 1.3046x over previous
#include <cuda_runtime.h>
#include <cuda_bf16.h>
#include <cstdint>
#include <cstddef>

#define BATCH    8
#define NPTS     8192
#define NPOINT_  1024
#define NSAMPLE_ 32
#define CFEAT    64
#define CSZ      4
#define PPC      (NPTS / CSZ)   // 2048 points per CTA

// scratch (device globals; no allocation allowed)
__device__ int   g_gidx[BATCH * NPOINT_ * NSAMPLE_];   // ball-query neighbor indices
__device__ float g_featproj[BATCH * NPTS * CFEAT];     // W1[:,3:] @ features per unique point

// ---------------- f32x2 helpers (Blackwell packed fp32; IEEE per lane) ------
__device__ __forceinline__ unsigned long long f2_pack(float a, float b) {
    unsigned long long r;
    asm("mov.b64 %0, {%1, %2};" : "=l"(r) : "r"(__float_as_uint(a)), "r"(__float_as_uint(b)));
    return r;
}
__device__ __forceinline__ unsigned long long f2_bcast(float a) {
    unsigned long long r;
    unsigned x = __float_as_uint(a);
    asm("mov.b64 %0, {%1, %1};" : "=l"(r) : "r"(x));
    return r;
}
__device__ __forceinline__ void f2_unpack(unsigned long long v, float& lo, float& hi) {
    unsigned a, b;
    asm("mov.b64 {%0, %1}, %2;" : "=r"(a), "=r"(b) : "l"(v));
    lo = __uint_as_float(a); hi = __uint_as_float(b);
}
__device__ __forceinline__ unsigned long long f2_add(unsigned long long a, unsigned long long b) {
    unsigned long long d;
    asm("add.rn.f32x2 %0, %1, %2;" : "=l"(d) : "l"(a), "l"(b));
    return d;
}
__device__ __forceinline__ unsigned long long f2_mul(unsigned long long a, unsigned long long b) {
    unsigned long long d;
    asm("mul.rn.f32x2 %0, %1, %2;" : "=l"(d) : "l"(a), "l"(b));
    return d;
}
__device__ __forceinline__ unsigned long long f2_fma(unsigned long long a, unsigned long long b,
                                                     unsigned long long c) {
    unsigned long long d;
    asm("fma.rn.f32x2 %0, %1, %2, %3;" : "=l"(d) : "l"(a), "l"(b), "l"(c));
    return d;
}
__device__ __forceinline__ unsigned smem_u32(const void* p) {
    return (unsigned)__cvta_generic_to_shared(p);
}

// ---------------------------------------------------------------------------
// Kernel 1: farthest point sampling. 4-CTA cluster per batch (32 CTAs).
// Each CTA: 2048 pts in f32x2 register pairs, full 8192-pt cloud in 96KB smem.
// Cross-CTA exchange: single 64-bit tagged word per CTA per iteration
// (distbits<<32 | (8191-idx) | parity<<31), plain DSMEM store, all threads
// spin on local mailbox with volatile vector loads. No mbarrier, no acquire.
// Double-buffered mailboxes; writer at it+2 implies all CTAs consumed it.
// Per-point arithmetic bit-identical to the passing scalar version.
// ---------------------------------------------------------------------------
__global__ void __cluster_dims__(CSZ, 1, 1) __launch_bounds__(512, 1)
fps_kernel(const float* __restrict__ xyz, float* __restrict__ newxyz)
{
    extern __shared__ float fsm[];
    float* sx = fsm;
    float* sy = fsm + NPTS;
    float* sz = fsm + 2 * NPTS;
    __shared__ __align__(16) unsigned long long mbox[2][CSZ];
    __shared__ unsigned long long wkey[16];

    const int t = threadIdx.x;
    unsigned rank;
    asm("mov.u32 %0, %%cluster_ctarank;" : "=r"(rank));
    const int b = blockIdx.x / CSZ;
    const float* xb = xyz + (size_t)b * NPTS * 3;

    for (int i = t; i < NPTS; i += 512) {
        sx[i] = xb[3 * i + 0];
        sy[i] = xb[3 * i + 1];
        sz[i] = xb[3 * i + 2];
    }
    if (t < 8) ((unsigned long long*)mbox)[t] = (1ull << 31);   // tag=1 != first expected tag 0
    __syncthreads();
    asm volatile("barrier.cluster.arrive.aligned;" ::: "memory");
    asm volatile("barrier.cluster.wait.aligned;" ::: "memory");

    // precompute remote mailbox addresses (warp0 lanes 0..3 send to peer 'lane')
    unsigned rmb0 = 0, rmb1 = 0;
    if (t < CSZ) {
        unsigned l0 = smem_u32(&mbox[0][rank]);
        unsigned l1 = smem_u32(&mbox[1][rank]);
        asm("mapa.shared::cluster.u32 %0, %1, %2;" : "=r"(rmb0) : "r"(l0), "r"(t));
        asm("mapa.shared::cluster.u32 %0, %1, %2;" : "=r"(rmb1) : "r"(l1), "r"(t));
    }

    const int base = (int)rank * PPC;
    unsigned long long px2[2], py2[2], pz2[2];
    float pd[4];
#pragma unroll
    for (int q = 0; q < 2; ++q) {
        int i0 = base + t + q * 1024;
        int i1 = i0 + 512;
        px2[q] = f2_pack(sx[i0], sx[i1]);
        py2[q] = f2_pack(sy[i0], sy[i1]);
        pz2[q] = f2_pack(sz[i0], sz[i1]);
        pd[2 * q] = 1e10f; pd[2 * q + 1] = 1e10f;
    }

    float lx = sx[0], ly = sy[0], lz = sz[0];
    if (rank == 0 && t == 0) {
        newxyz[b * NPOINT_ * 3 + 0] = lx;
        newxyz[b * NPOINT_ * 3 + 1] = ly;
        newxyz[b * NPOINT_ * 3 + 2] = lz;
    }
    const int lane = t & 31, wid = t >> 5;
    const unsigned mbA = smem_u32(&mbox[0][0]);
    int ph0 = 0, ph1 = 0;

    for (int it = 1; it < NPOINT_; ++it) {
        const unsigned long long nlx = f2_bcast(-lx);
        const unsigned long long nly = f2_bcast(-ly);
        const unsigned long long nlz = f2_bcast(-lz);
#pragma unroll
        for (int q = 0; q < 2; ++q) {
            unsigned long long dx = f2_add(px2[q], nlx);
            unsigned long long dy = f2_add(py2[q], nly);
            unsigned long long dz = f2_add(pz2[q], nlz);
            unsigned long long d2 = f2_fma(dx, dx, f2_fma(dy, dy, f2_mul(dz, dz)));
            float d0, d1;
            f2_unpack(d2, d0, d1);
            pd[2 * q]     = fminf(pd[2 * q],     d0);
            pd[2 * q + 1] = fminf(pd[2 * q + 1], d1);
        }
        const float vmax = fmaxf(fmaxf(pd[0], pd[1]), fmaxf(pd[2], pd[3]));
        unsigned msk = 0;
#pragma unroll
        for (int j = 0; j < 4; ++j) msk |= (pd[j] == vmax) ? (1u << j) : 0u;
        const int bj = __ffs(msk) - 1;
        const unsigned gi = (unsigned)(base + t + bj * 512);

        const unsigned vb = __float_as_uint(vmax);
        const unsigned wm = __reduce_max_sync(0xffffffffu, vb);
        const unsigned cand = (vb == wm) ? gi : 0xffffffffu;
        const unsigned wi = __reduce_min_sync(0xffffffffu, cand);

        if (lane == 0) wkey[wid] = ((unsigned long long)wm << 32) | (unsigned)(8191 - wi);
        __syncthreads();

        const int buf = it & 1;
        const unsigned tag = (unsigned)(buf ? ph1 : ph0);
        if (wid == 0) {
            const unsigned long long k = wkey[lane & 15];
            const unsigned hi = (unsigned)(k >> 32);
            const unsigned lo = (unsigned)k;
            const unsigned hm = __reduce_max_sync(0xffffffffu, hi);
            const unsigned cl = (hi == hm) ? lo : 0u;
            const unsigned lm = __reduce_max_sync(0xffffffffu, cl);
            const unsigned long long ck = ((unsigned long long)hm << 32)
                                        | (unsigned long long)(lm | (tag << 31));
            if (lane < CSZ) {
                const unsigned dst = buf ? rmb1 : rmb0;
                asm volatile("st.shared::cluster.b64 [%0], %1;" :: "r"(dst), "l"(ck) : "memory");
            }
        }
        // all threads spin on the local 4-word mailbox (parity tag in bit31 low word)
        const unsigned a0 = mbA + (unsigned)buf * (CSZ * 8);
        unsigned long long k0, k1, k2, k3;
        for (;;) {
            asm volatile("ld.volatile.shared.v2.u64 {%0,%1}, [%2];"
                         : "=l"(k0), "=l"(k1) : "r"(a0));
            asm volatile("ld.volatile.shared.v2.u64 {%0,%1}, [%2];"
                         : "=l"(k2), "=l"(k3) : "r"(a0 + 16));
            unsigned bad = (((unsigned)(k0 >> 31) ^ tag) | ((unsigned)(k1 >> 31) ^ tag)
                          | ((unsigned)(k2 >> 31) ^ tag) | ((unsigned)(k3 >> 31) ^ tag)) & 1u;
            if (!bad) break;
        }
        if (buf) ph1 ^= 1; else ph0 ^= 1;

        unsigned long long m01 = (k0 > k1) ? k0 : k1;
        unsigned long long m23 = (k2 > k3) ? k2 : k3;
        unsigned long long km  = (m01 > m23) ? m01 : m23;
        const int win = 8191 - (int)((unsigned)km & 0x7fffffffu);
        lx = sx[win]; ly = sy[win]; lz = sz[win];
        if (rank == 0 && t == 0) {
            newxyz[(b * NPOINT_ + it) * 3 + 0] = lx;
            newxyz[(b * NPOINT_ + it) * 3 + 1] = ly;
            newxyz[(b * NPOINT_ + it) * 3 + 2] = lz;
        }
    }
    asm volatile("barrier.cluster.arrive.aligned;" ::: "memory");
    asm volatile("barrier.cluster.wait.aligned;" ::: "memory");
}

// ---------------------------------------------------------------------------
// Kernel 2: layer-1 feature projection for all unique points.
// ---------------------------------------------------------------------------
__global__ void __launch_bounds__(256) featproj_kernel(const float* __restrict__ feat,
                                                       const float* __restrict__ w1)
{
    __shared__ float ws[64 * 65];
    __shared__ float sf[8][64];

    const int tid = threadIdx.x;
    for (int i = tid; i < 64 * 64; i += 256) {
        int o = i >> 6, c = i & 63;
        ws[o * 65 + c] = w1[o * 67 + 3 + c];
    }
    __syncthreads();

    const int wid = tid >> 5, lane = tid & 31;
    const int row = blockIdx.x * 8 + wid;
    const float* fr = feat + (size_t)row * 64;
    sf[wid][lane]      = fr[lane];
    sf[wid][lane + 32] = fr[lane + 32];
    __syncwarp();

    float a0 = 0.f, a1 = 0.f;
#pragma unroll
    for (int c = 0; c < 64; ++c) {
        float f = sf[wid][c];
        a0 = fmaf(ws[lane * 65 + c],        f, a0);
        a1 = fmaf(ws[(lane + 32) * 65 + c], f, a1);
    }
    float* outr = g_featproj + (size_t)row * 64;
    outr[lane]      = a0;
    outr[lane + 32] = a1;
}

// ---------------------------------------------------------------------------
// Kernel 3: ball query. One warp per center; first-32-by-index, pad with first.
// ---------------------------------------------------------------------------
__global__ void __launch_bounds__(256) ballquery_kernel(const float* __restrict__ xyz,
                                                        const float* __restrict__ newxyz)
{
    const int gw = (blockIdx.x * blockDim.x + threadIdx.x) >> 5;
    const int lane = threadIdx.x & 31;
    const int b = gw >> 10;
    const float* xb = xyz + (size_t)b * NPTS * 3;
    const float cx = newxyz[gw * 3 + 0];
    const float cy = newxyz[gw * 3 + 1];
    const float cz = newxyz[gw * 3 + 2];
    int* out = g_gidx + gw * 32;

    const float R2 = (float)(0.4 * 0.4);
    int cnt = 0, first = 0;
    bool hasfirst = false;
    for (int p0 = 0; p0 < NPTS && cnt < 32; p0 += 32) {
        int p = p0 + lane;
        float dx = xb[p * 3 + 0] - cx;
        float dy = xb[p * 3 + 1] - cy;
        float dz = xb[p * 3 + 2] - cz;
        float d2 = fmaf(dx, dx, fmaf(dy, dy, dz * dz));
        bool in = d2 < R2;
        unsigned mask = __ballot_sync(0xffffffffu, in);
        if (mask) {
            if (!hasfirst) { first = p0 + __ffs(mask) - 1; hasfirst = true; }
            int ofs = cnt + __popc(mask & ((1u << lane) - 1u));
            if (in && ofs < 32) out[ofs] = p;
            cnt += __popc(mask);
        }
    }
    for (int s = cnt + lane; s < 32; s += 32) out[s] = first;
}

// ---------------------------------------------------------------------------
// Kernel 4: fused gather + 3-layer MLP + max-pool. Warp per center, lane = sample.
// Layers 2/3 in packed f32x2; maxpool via REDUX on nonneg float bits.
// ---------------------------------------------------------------------------
__global__ void __launch_bounds__(128) mlp_kernel(
    const float* __restrict__ xyz,
    const float* __restrict__ w1, const float* __restrict__ b1,
    const float* __restrict__ w2, const float* __restrict__ b2,
    const float* __restrict__ w3, const float* __restrict__ b3,
    float* __restrict__ d_out)
{
    extern __shared__ float sm[];
    float4* sw1p = (float4*)sm;
    float*  sb2  = sm + 256;
    float*  sb3  = sm + 320;
    float*  sw2t = sm + 448;
    unsigned long long* sw3p = (unsigned long long*)(sm + 4544);
    float*  sout = sm + 12736;

    const int tid = threadIdx.x;
    const int wid = tid >> 5, lane = tid & 31;
    const int center0 = blockIdx.x * 4;
    const int center = center0 + wid;
    const int b = center >> 10;
    const int m0 = center0 & 1023;

    if (tid < 64) {
        sw1p[tid] = make_float4(w1[tid * 67 + 0], w1[tid * 67 + 1], w1[tid * 67 + 2], b1[tid]);
        sb2[tid] = b2[tid];
    }
    if (tid < 128) sb3[tid] = b3[tid];
    for (int i = tid; i < 4096; i += 128) sw2t[i] = w2[(i & 63) * 64 + (i >> 6)];
    for (int i = tid; i < 4096; i += 128) {
        int c2 = i >> 7, o = i & 127;
        ((float2*)sw3p)[i] = make_float2(w3[o * 64 + 2 * c2], w3[o * 64 + 2 * c2 + 1]);
    }
    __syncthreads();

    const float* newxyz = d_out;              // written by fps_kernel
    const float cx = newxyz[center * 3 + 0];
    const float cy = newxyz[center * 3 + 1];
    const float cz = newxyz[center * 3 + 2];

    const int ni = g_gidx[center * 32 + lane];
    const float* p = xyz + ((size_t)b * NPTS + ni) * 3;
    const float dx = p[0] - cx, dy = p[1] - cy, dz = p[2] - cz;

    // ---- layers 1+2 fused; h2 accumulated as output-pairs in f32x2 ----
    unsigned long long h2p[32];
#pragma unroll
    for (int k = 0; k < 32; ++k) h2p[k] = ((const unsigned long long*)sb2)[k];

    const float4* fp4 = (const float4*)(g_featproj + ((size_t)b * NPTS + ni) * 64);
#pragma unroll 1
    for (int cc = 0; cc < 16; ++cc) {
        float4 f = fp4[cc];
        float fv[4] = {f.x, f.y, f.z, f.w};
#pragma unroll
        for (int j = 0; j < 4; ++j) {
            int c = cc * 4 + j;
            float4 wp = sw1p[c];
            float a = fmaf(wp.x, dx, fv[j]);
            a = fmaf(wp.y, dy, a);
            a = fmaf(wp.z, dz, a);
            a = fmaxf(a + wp.w, 0.0f);
            const unsigned long long a2 = f2_bcast(a);
            const ulonglong2* wrow = (const ulonglong2*)(sw2t + c * 64);
#pragma unroll
            for (int k2 = 0; k2 < 16; ++k2) {
                ulonglong2 w = wrow[k2];
                h2p[2 * k2 + 0] = f2_fma(w.x, a2, h2p[2 * k2 + 0]);
                h2p[2 * k2 + 1] = f2_fma(w.y, a2, h2p[2 * k2 + 1]);
            }
        }
    }
#pragma unroll
    for (int k = 0; k < 32; ++k) {
        float lo, hi;
        f2_unpack(h2p[k], lo, hi);
        h2p[k] = f2_pack(fmaxf(lo, 0.0f), fmaxf(hi, 0.0f));
    }

    // ---- layer 3 (c-paired f32x2, even/odd partial sums) + REDUX max-pool ----
#pragma unroll 1
    for (int o8 = 0; o8 < 16; ++o8) {
        unsigned long long acc[8];
#pragma unroll
        for (int j = 0; j < 8; ++j) acc[j] = f2_pack(sb3[o8 * 8 + j], 0.0f);
#pragma unroll
        for (int c2 = 0; c2 < 32; ++c2) {
            const unsigned long long a = h2p[c2];
            const ulonglong2* wr = (const ulonglong2*)(sw3p + c2 * 128 + o8 * 8);
            ulonglong2 wa = wr[0], wb = wr[1], wc = wr[2], wd = wr[3];
            acc[0] = f2_fma(wa.x, a, acc[0]);
            acc[1] = f2_fma(wa.y, a, acc[1]);
            acc[2] = f2_fma(wb.x, a, acc[2]);
            acc[3] = f2_fma(wb.y, a, acc[3]);
            acc[4] = f2_fma(wc.x, a, acc[4]);
            acc[5] = f2_fma(wc.y, a, acc[5]);
            acc[6] = f2_fma(wd.x, a, acc[6]);
            acc[7] = f2_fma(wd.y, a, acc[7]);
        }
#pragma unroll
        for (int j = 0; j < 8; ++j) {
            float e, od;
            f2_unpack(acc[j], e, od);
            float v = fmaxf(e + od, 0.0f);
            unsigned r = __reduce_max_sync(0xffffffffu, __float_as_uint(v));
            if (lane == 0) sout[(o8 * 8 + j) * 4 + wid] = __uint_as_float(r);
        }
    }
    __syncthreads();

    float* nf = d_out + BATCH * NPOINT_ * 3;
    const int o = tid;
    float4 v = *(float4*)&sout[o * 4];
    *(float4*)&nf[((size_t)b * 128 + o) * (size_t)NPOINT_ + m0] = v;
}

// ---------------------------------------------------------------------------
extern "C" void kernel_launch(void* const* d_in, const int* in_sizes, int n_in,
                              void* d_out, int out_size)
{
    const float* xyz      = (const float*)d_in[0];
    const float* features = (const float*)d_in[1];
    const float* w1 = (const float*)d_in[2];
    const float* b1 = (const float*)d_in[3];
    const float* w2 = (const float*)d_in[4];
    const float* b2 = (const float*)d_in[5];
    const float* w3 = (const float*)d_in[6];
    const float* b3 = (const float*)d_in[7];
    float* out = (float*)d_out;

    cudaFuncSetAttribute(fps_kernel, cudaFuncAttributeMaxDynamicSharedMemorySize, NPTS * 3 * 4);
    cudaFuncSetAttribute(mlp_kernel, cudaFuncAttributeMaxDynamicSharedMemorySize, 13248 * 4);

    featproj_kernel<<<8192, 256>>>(features, w1);
    fps_kernel<<<BATCH * CSZ, 512, NPTS * 3 * 4>>>(xyz, out);
    ballquery_kernel<<<1024, 256>>>(xyz, out);
    mlp_kernel<<<2048, 128, 13248 * 4>>>(xyz, w1, b1, w2, b2, w3, b3, out);
}